// round 1
// baseline (speedup 1.0000x reference)
#include <cuda_runtime.h>

// VectorKuramoto: out[b,i,d] = th + omega + kappa*(gamma-th)
//                  + (1/N) * sum_j A[b,i,j]*sin(th[b,j,d]-th[b,i,d]-(alpha_t[b,i,j]+alpha_bias[i,j]))
// Factorized: sum_j A*sin(tj-ti-a) = ci*P - si*Q with
//   P = sum_j (A*cos(a))*sj - (A*sin(a))*cj
//   Q = sum_j (A*cos(a))*cj + (A*sin(a))*sj

namespace {

constexpr int Bb = 4;
constexpr int Nn = 2048;
constexpr int Dd = 4;
constexpr int N4 = Nn / 4;              // float4 count along j
constexpr int THREADS = 256;            // 8 warps
constexpr int ROWS_PER_BLOCK = 32;      // 8 warps x 4 rows
constexpr int ROWS_PER_WARP = 4;

// padded smem layout to kill LDS.128 bank conflicts (stride-16-word pattern)
__device__ __host__ __forceinline__ int padidx(int i) { return i + (i >> 3); }
constexpr int PAD_N = Nn + (Nn >> 3);   // 2304 float4 slots per table
constexpr int SMEM_BYTES = 2 * PAD_N * (int)sizeof(float4);  // 73728 B

__device__ __forceinline__ void accum(float A, float a,
                                      const float4 sj, const float4 cj,
                                      float4& P, float4& Q) {
    float sa, ca;
    __sincosf(a, &sa, &ca);
    float w1 = A * ca;
    float w2 = A * sa;
    P.x = fmaf(w1, sj.x, fmaf(-w2, cj.x, P.x));
    P.y = fmaf(w1, sj.y, fmaf(-w2, cj.y, P.y));
    P.z = fmaf(w1, sj.z, fmaf(-w2, cj.z, P.z));
    P.w = fmaf(w1, sj.w, fmaf(-w2, cj.w, P.w));
    Q.x = fmaf(w1, cj.x, fmaf(w2, sj.x, Q.x));
    Q.y = fmaf(w1, cj.y, fmaf(w2, sj.y, Q.y));
    Q.z = fmaf(w1, cj.z, fmaf(w2, sj.z, Q.z));
    Q.w = fmaf(w1, cj.w, fmaf(w2, sj.w, Q.w));
}

} // namespace

extern "C" __global__ void __launch_bounds__(THREADS, 2)
vector_kuramoto_kernel(const float4* __restrict__ theta4,
                       const float4* __restrict__ gamma4,
                       const float4* __restrict__ aff4,
                       const float4* __restrict__ alpha4,
                       const float4* __restrict__ omega4,
                       const float4* __restrict__ kappa4,
                       const float4* __restrict__ abias4,
                       float4* __restrict__ out4)
{
    extern __shared__ float4 smem[];
    float4* s4 = smem;            // sin(theta[b, r, :]) at padidx(r)
    float4* c4 = smem + PAD_N;    // cos(theta[b, r, :]) at padidx(r)

    const int b   = blockIdx.y;
    const int tid = threadIdx.x;

    // Fill per-batch sincos tables. theta[b, r, :] is exactly one float4 (D=4).
    for (int r = tid; r < Nn; r += THREADS) {
        float4 th = theta4[b * Nn + r];
        float4 s, c;
        __sincosf(th.x, &s.x, &c.x);
        __sincosf(th.y, &s.y, &c.y);
        __sincosf(th.z, &s.z, &c.z);
        __sincosf(th.w, &s.w, &c.w);
        s4[padidx(r)] = s;
        c4[padidx(r)] = c;
    }
    __syncthreads();

    const int warp = tid >> 5;
    const int lane = tid & 31;
    const int r0 = blockIdx.x * ROWS_PER_BLOCK + warp * ROWS_PER_WARP;

    float4 P[ROWS_PER_WARP], Q[ROWS_PER_WARP];
    #pragma unroll
    for (int k = 0; k < ROWS_PER_WARP; ++k) {
        P[k] = make_float4(0.f, 0.f, 0.f, 0.f);
        Q[k] = make_float4(0.f, 0.f, 0.f, 0.f);
    }

    // Each lane walks float4-chunks of j (coalesced LDG.128 across the warp).
    #pragma unroll 1
    for (int jb = lane; jb < N4; jb += 32) {
        const int j0 = jb * 4;
        float4 sj0 = s4[padidx(j0 + 0)], cj0 = c4[padidx(j0 + 0)];
        float4 sj1 = s4[padidx(j0 + 1)], cj1 = c4[padidx(j0 + 1)];
        float4 sj2 = s4[padidx(j0 + 2)], cj2 = c4[padidx(j0 + 2)];
        float4 sj3 = s4[padidx(j0 + 3)], cj3 = c4[padidx(j0 + 3)];
        #pragma unroll
        for (int k = 0; k < ROWS_PER_WARP; ++k) {
            const int i = r0 + k;
            const int rowbase = (b * Nn + i) * N4;   // fits in int (max ~4.2M)
            float4 A  = aff4[rowbase + jb];
            float4 at = alpha4[rowbase + jb];
            float4 ab = abias4[i * N4 + jb];
            accum(A.x, at.x + ab.x, sj0, cj0, P[k], Q[k]);
            accum(A.y, at.y + ab.y, sj1, cj1, P[k], Q[k]);
            accum(A.z, at.z + ab.z, sj2, cj2, P[k], Q[k]);
            accum(A.w, at.w + ab.w, sj3, cj3, P[k], Q[k]);
        }
    }

    // Warp-level sum reduction of the 8 accumulators per row.
    #pragma unroll
    for (int k = 0; k < ROWS_PER_WARP; ++k) {
        #pragma unroll
        for (int off = 16; off; off >>= 1) {
            P[k].x += __shfl_down_sync(0xffffffffu, P[k].x, off);
            P[k].y += __shfl_down_sync(0xffffffffu, P[k].y, off);
            P[k].z += __shfl_down_sync(0xffffffffu, P[k].z, off);
            P[k].w += __shfl_down_sync(0xffffffffu, P[k].w, off);
            Q[k].x += __shfl_down_sync(0xffffffffu, Q[k].x, off);
            Q[k].y += __shfl_down_sync(0xffffffffu, Q[k].y, off);
            Q[k].z += __shfl_down_sync(0xffffffffu, Q[k].z, off);
            Q[k].w += __shfl_down_sync(0xffffffffu, Q[k].w, off);
        }
    }

    if (lane == 0) {
        const float inv = 1.0f / (float)Nn;   // COUPLING=1, DT=1
        #pragma unroll
        for (int k = 0; k < ROWS_PER_WARP; ++k) {
            const int i = r0 + k;
            float4 th = theta4[b * Nn + i];
            float4 si = s4[padidx(i)];
            float4 ci = c4[padidx(i)];
            float4 g  = gamma4[b * Nn + i];
            float4 om = omega4[i];
            float4 kp = kappa4[i];
            float4 o;
            o.x = th.x + om.x + kp.x * (g.x - th.x) + inv * (ci.x * P[k].x - si.x * Q[k].x);
            o.y = th.y + om.y + kp.y * (g.y - th.y) + inv * (ci.y * P[k].y - si.y * Q[k].y);
            o.z = th.z + om.z + kp.z * (g.z - th.z) + inv * (ci.z * P[k].z - si.z * Q[k].z);
            o.w = th.w + om.w + kp.w * (g.w - th.w) + inv * (ci.w * P[k].w - si.w * Q[k].w);
            out4[b * Nn + i] = o;
        }
    }
}

extern "C" void kernel_launch(void* const* d_in, const int* in_sizes, int n_in,
                              void* d_out, int out_size) {
    (void)in_sizes; (void)n_in; (void)out_size;
    const float4* theta4 = (const float4*)d_in[0];
    const float4* gamma4 = (const float4*)d_in[1];
    const float4* aff4   = (const float4*)d_in[2];
    const float4* alpha4 = (const float4*)d_in[3];
    const float4* omega4 = (const float4*)d_in[4];
    const float4* kappa4 = (const float4*)d_in[5];
    const float4* abias4 = (const float4*)d_in[6];
    float4* out4 = (float4*)d_out;

    static bool attr_set = false;
    if (!attr_set) {
        cudaFuncSetAttribute(vector_kuramoto_kernel,
                             cudaFuncAttributeMaxDynamicSharedMemorySize, SMEM_BYTES);
        attr_set = true;
    }

    dim3 grid(Nn / ROWS_PER_BLOCK, Bb);   // (64, 4)
    vector_kuramoto_kernel<<<grid, THREADS, SMEM_BYTES>>>(
        theta4, gamma4, aff4, alpha4, omega4, kappa4, abias4, out4);
}

// round 2
// speedup vs baseline: 1.0883x; 1.0883x over previous
#include <cuda_runtime.h>

// VectorKuramoto factorized:
//   sum_j A*sin(tj - ti - a) = ci*P - si*Q
//   P = sum_j (A cos a) sj - (A sin a) cj
//   Q = sum_j (A cos a) cj + (A sin a) sj
// One sincos per (b,i,j); D=4 handled with packed f32x2 FMA.

namespace {

constexpr int Bb = 4;
constexpr int Nn = 2048;
constexpr int N4 = Nn / 4;               // float4 chunks along j
constexpr int THREADS = 512;             // 16 warps
constexpr int ROWS_PER_WARP = 2;
constexpr int ROWS_PER_BLOCK = 32;       // 16 warps x 2 rows

__device__ __host__ __forceinline__ int padidx(int i) { return i + (i >> 3); }
constexpr int PAD_N = Nn + (Nn >> 3);    // 2304 float4 slots per table
constexpr int SMEM_BYTES = 2 * PAD_N * (int)sizeof(float4);  // 73728 B

typedef unsigned long long ull;

#define FMA2(d, a, b, c) \
    asm("fma.rn.f32x2 %0, %1, %2, %3;" : "=l"(d) : "l"(a), "l"(b), "l"(c))
#define PACK2(d, lo, hi) \
    asm("mov.b64 %0, {%1, %2};" : "=l"(d) : "f"(lo), "f"(hi))
#define UNPACK2(lo, hi, s) \
    asm("mov.b64 {%0, %1}, %2;" : "=f"(lo), "=f"(hi) : "l"(s))

union F4U { float4 v; ull u[2]; };

__device__ __forceinline__ void cell(float A, float a,
                                     ull sj01, ull sj23, ull cj01, ull cj23,
                                     ull& Pa, ull& Pb, ull& Qa, ull& Qb)
{
    float sa, ca;
    __sincosf(a, &sa, &ca);
    float w1 = A * ca;
    float w2 = A * sa;
    float nw2 = -w2;
    ull pw1, pw2, pnw2;
    PACK2(pw1, w1, w1);
    PACK2(pw2, w2, w2);
    PACK2(pnw2, nw2, nw2);
    FMA2(Pa, pnw2, cj01, Pa); FMA2(Pa, pw1, sj01, Pa);
    FMA2(Pb, pnw2, cj23, Pb); FMA2(Pb, pw1, sj23, Pb);
    FMA2(Qa, pw2,  sj01, Qa); FMA2(Qa, pw1, cj01, Qa);
    FMA2(Qb, pw2,  sj23, Qb); FMA2(Qb, pw1, cj23, Qb);
}

} // namespace

extern "C" __global__ void __launch_bounds__(THREADS, 2)
vector_kuramoto_kernel(const float4* __restrict__ theta4,
                       const float4* __restrict__ gamma4,
                       const float4* __restrict__ aff4,
                       const float4* __restrict__ alpha4,
                       const float4* __restrict__ omega4,
                       const float4* __restrict__ kappa4,
                       const float4* __restrict__ abias4,
                       float4* __restrict__ out4)
{
    extern __shared__ float4 smem[];
    float4* s4 = smem;            // sin(theta[b, r, :]) at padidx(r)
    float4* c4 = smem + PAD_N;    // cos(theta[b, r, :]) at padidx(r)

    const int b   = blockIdx.y;
    const int tid = threadIdx.x;

    // Per-batch sincos tables (theta[b,r,:] is one float4, D=4).
    for (int r = tid; r < Nn; r += THREADS) {
        float4 th = theta4[b * Nn + r];
        float4 s, c;
        __sincosf(th.x, &s.x, &c.x);
        __sincosf(th.y, &s.y, &c.y);
        __sincosf(th.z, &s.z, &c.z);
        __sincosf(th.w, &s.w, &c.w);
        s4[padidx(r)] = s;
        c4[padidx(r)] = c;
    }
    __syncthreads();

    const int warp = tid >> 5;
    const int lane = tid & 31;
    const int i0 = blockIdx.x * ROWS_PER_BLOCK + warp * ROWS_PER_WARP;
    const int i1 = i0 + 1;

    // 32-bit row bases (max index ~4.2M float4s)
    const int rb0 = (b * Nn + i0) * N4;
    const int rb1 = (b * Nn + i1) * N4;
    const int bb0 = i0 * N4;
    const int bb1 = i1 * N4;

    ull P0a = 0, P0b = 0, Q0a = 0, Q0b = 0;
    ull P1a = 0, P1b = 0, Q1a = 0, Q1b = 0;

    #pragma unroll 1
    for (int jb = lane; jb < N4; jb += 32) {
        float4 A0 = __ldcs(aff4   + rb0 + jb);
        float4 T0 = __ldcs(alpha4 + rb0 + jb);
        float4 B0 = abias4[bb0 + jb];
        float4 A1 = __ldcs(aff4   + rb1 + jb);
        float4 T1 = __ldcs(alpha4 + rb1 + jb);
        float4 B1 = abias4[bb1 + jb];

        const int j0 = jb * 4;

        F4U sj, cj;
        sj.v = s4[padidx(j0 + 0)]; cj.v = c4[padidx(j0 + 0)];
        cell(A0.x, T0.x + B0.x, sj.u[0], sj.u[1], cj.u[0], cj.u[1], P0a, P0b, Q0a, Q0b);
        cell(A1.x, T1.x + B1.x, sj.u[0], sj.u[1], cj.u[0], cj.u[1], P1a, P1b, Q1a, Q1b);

        sj.v = s4[padidx(j0 + 1)]; cj.v = c4[padidx(j0 + 1)];
        cell(A0.y, T0.y + B0.y, sj.u[0], sj.u[1], cj.u[0], cj.u[1], P0a, P0b, Q0a, Q0b);
        cell(A1.y, T1.y + B1.y, sj.u[0], sj.u[1], cj.u[0], cj.u[1], P1a, P1b, Q1a, Q1b);

        sj.v = s4[padidx(j0 + 2)]; cj.v = c4[padidx(j0 + 2)];
        cell(A0.z, T0.z + B0.z, sj.u[0], sj.u[1], cj.u[0], cj.u[1], P0a, P0b, Q0a, Q0b);
        cell(A1.z, T1.z + B1.z, sj.u[0], sj.u[1], cj.u[0], cj.u[1], P1a, P1b, Q1a, Q1b);

        sj.v = s4[padidx(j0 + 3)]; cj.v = c4[padidx(j0 + 3)];
        cell(A0.w, T0.w + B0.w, sj.u[0], sj.u[1], cj.u[0], cj.u[1], P0a, P0b, Q0a, Q0b);
        cell(A1.w, T1.w + B1.w, sj.u[0], sj.u[1], cj.u[0], cj.u[1], P1a, P1b, Q1a, Q1b);
    }

    // Unpack accumulators and warp-reduce.
    float p0[4], q0[4], p1[4], q1[4];
    UNPACK2(p0[0], p0[1], P0a); UNPACK2(p0[2], p0[3], P0b);
    UNPACK2(q0[0], q0[1], Q0a); UNPACK2(q0[2], q0[3], Q0b);
    UNPACK2(p1[0], p1[1], P1a); UNPACK2(p1[2], p1[3], P1b);
    UNPACK2(q1[0], q1[1], Q1a); UNPACK2(q1[2], q1[3], Q1b);

    #pragma unroll
    for (int off = 16; off; off >>= 1) {
        #pragma unroll
        for (int d = 0; d < 4; ++d) {
            p0[d] += __shfl_down_sync(0xffffffffu, p0[d], off);
            q0[d] += __shfl_down_sync(0xffffffffu, q0[d], off);
            p1[d] += __shfl_down_sync(0xffffffffu, p1[d], off);
            q1[d] += __shfl_down_sync(0xffffffffu, q1[d], off);
        }
    }

    if (lane == 0) {
        const float inv = 1.0f / (float)Nn;   // COUPLING=1, DT=1
        {
            const int i = i0;
            float4 th = theta4[b * Nn + i];
            float4 si = s4[padidx(i)];
            float4 ci = c4[padidx(i)];
            float4 g  = gamma4[b * Nn + i];
            float4 om = omega4[i];
            float4 kp = kappa4[i];
            float4 o;
            o.x = th.x + om.x + kp.x * (g.x - th.x) + inv * (ci.x * p0[0] - si.x * q0[0]);
            o.y = th.y + om.y + kp.y * (g.y - th.y) + inv * (ci.y * p0[1] - si.y * q0[1]);
            o.z = th.z + om.z + kp.z * (g.z - th.z) + inv * (ci.z * p0[2] - si.z * q0[2]);
            o.w = th.w + om.w + kp.w * (g.w - th.w) + inv * (ci.w * p0[3] - si.w * q0[3]);
            out4[b * Nn + i] = o;
        }
        {
            const int i = i1;
            float4 th = theta4[b * Nn + i];
            float4 si = s4[padidx(i)];
            float4 ci = c4[padidx(i)];
            float4 g  = gamma4[b * Nn + i];
            float4 om = omega4[i];
            float4 kp = kappa4[i];
            float4 o;
            o.x = th.x + om.x + kp.x * (g.x - th.x) + inv * (ci.x * p1[0] - si.x * q1[0]);
            o.y = th.y + om.y + kp.y * (g.y - th.y) + inv * (ci.y * p1[1] - si.y * q1[1]);
            o.z = th.z + om.z + kp.z * (g.z - th.z) + inv * (ci.z * p1[2] - si.z * q1[2]);
            o.w = th.w + om.w + kp.w * (g.w - th.w) + inv * (ci.w * p1[3] - si.w * q1[3]);
            out4[b * Nn + i] = o;
        }
    }
}

extern "C" void kernel_launch(void* const* d_in, const int* in_sizes, int n_in,
                              void* d_out, int out_size) {
    (void)in_sizes; (void)n_in; (void)out_size;
    const float4* theta4 = (const float4*)d_in[0];
    const float4* gamma4 = (const float4*)d_in[1];
    const float4* aff4   = (const float4*)d_in[2];
    const float4* alpha4 = (const float4*)d_in[3];
    const float4* omega4 = (const float4*)d_in[4];
    const float4* kappa4 = (const float4*)d_in[5];
    const float4* abias4 = (const float4*)d_in[6];
    float4* out4 = (float4*)d_out;

    static bool attr_set = false;
    if (!attr_set) {
        cudaFuncSetAttribute(vector_kuramoto_kernel,
                             cudaFuncAttributeMaxDynamicSharedMemorySize, SMEM_BYTES);
        attr_set = true;
    }

    dim3 grid(Nn / ROWS_PER_BLOCK, Bb);   // (64, 4)
    vector_kuramoto_kernel<<<grid, THREADS, SMEM_BYTES>>>(
        theta4, gamma4, aff4, alpha4, omega4, kappa4, abias4, out4);
}